// round 15
// baseline (speedup 1.0000x reference)
#include <cuda_runtime.h>
#include <math.h>

// ChamferReward — R14: single-pass dual-axis chamfer. The two directions share
// one distance matrix (P is computed twice in the 2-pass champion). One CTA per
// (b,view): 512 CTAs x 128 thr, ITEMS=8 states/thread (consecutive i), goals
// staged in smem. Per-state: champion chunk-fold+rescan on full d. Per-goal:
// thread ascending-k strict-< fold -> warp value butterfly + ballot/ffs (lowest
// lane = lowest i) -> lane0 atomicMin.u64 smem slot keyed (mono(v)<<32|i):
// exact lexicographic (value, first-index) min. FFMA2 count halved (the proven
// rt~4 FFMA2 issue ceiling is the wall).

#define N_PART  1024
#define NJP     512
#define THREADS 128
#define ITEMS   8
#define CJP     8               // jp per chunk (16 j)
#define NCHUNK  (NJP / CJP)     // 64
#define NCTA    512

typedef unsigned long long ull;

__device__ float g_partials[NCTA];
__device__ unsigned int g_arrived = 0;

#define FMA2(d, a, b, c) \
    asm("fma.rn.f32x2 %0, %1, %2, %3;" : "=l"(d) : "l"(a), "l"(b), "l"(c))

__device__ __forceinline__ ull pack_dup(float x) {
    ull r;
    unsigned xi = __float_as_uint(x);
    asm("mov.b64 %0, {%1, %1};" : "=l"(r) : "r"(xi));
    return r;
}

__device__ __forceinline__ void unpack2(ull v, float& lo, float& hi) {
    unsigned a, b;
    asm("mov.b64 {%0, %1}, %2;" : "=r"(a), "=r"(b) : "l"(v));
    lo = __uint_as_float(a);
    hi = __uint_as_float(b);
}

// Order-preserving f32 -> u32 (total order; all our d values are ordinary).
__device__ __forceinline__ unsigned mono_f32(float f) {
    unsigned u = __float_as_uint(f);
    return ((int)u < 0) ? ~u : (u | 0x80000000u);
}
__device__ __forceinline__ float unmono_f32(unsigned m) {
    unsigned u = (m & 0x80000000u) ? (m & 0x7FFFFFFFu) : ~m;
    return __uint_as_float(u);
}

__global__ void __launch_bounds__(THREADS, 4)
chamfer_pass_kernel(const float* __restrict__ achieved,
                    const float* __restrict__ desired,
                    const float* __restrict__ norm_mean,
                    const float* __restrict__ norm_std,
                    float* __restrict__ out)
{
    __shared__ ulonglong2 sb01[NJP];   // 8KB: goal {b0 pair, b1 pair}
    __shared__ ulonglong2 sb23[NJP];   // 8KB: goal {b2 pair, b3 pair}
    __shared__ ull        sbb[NJP];    // 4KB: goal |g|^2 pair
    __shared__ float2     sxy[N_PART]; // 8KB: goal xy (normalized)
    __shared__ ull        slotj[N_PART]; // 8KB: per-goal (mono(d)<<32 | state_i)
    __shared__ float      warp_sums[THREADS / 32];
    __shared__ unsigned int s_rank;

    const int bv  = blockIdx.x;        // (b, view) slice
    const float* ownp = achieved + (size_t)bv * N_PART * 10;  // states (rows i)
    const float* strp = desired  + (size_t)bv * N_PART * 10;  // goals  (cols j)

    const float m0 = __ldg(norm_mean + 0), m1 = __ldg(norm_mean + 1);
    const float m5 = __ldg(norm_mean + 5), m6 = __ldg(norm_mean + 6);
    const float m7 = __ldg(norm_mean + 7), m8 = __ldg(norm_mean + 8);
    const float s0 = __ldg(norm_std  + 0), s1 = __ldg(norm_std  + 1);
    const float s5 = __ldg(norm_std  + 5), s6 = __ldg(norm_std  + 6);
    const float s7 = __ldg(norm_std  + 7), s8 = __ldg(norm_std  + 8);

    const int tid  = threadIdx.x;
    const int lane = tid & 31;

    // ---- Stage goals (normalize, precompute |g|^2); init per-goal slots ----
    {
        float* f01 = (float*)sb01;
        float* f23 = (float*)sb23;
        float* fbb = (float*)sbb;
        for (int j = tid; j < N_PART; j += THREADS) {
            const float2* r2 = (const float2*)(strp + (size_t)j * 10);
            const float2 q0 = r2[0];
            const float2 q1 = r2[2];
            const float2 q2 = r2[3];
            const float2 q3 = r2[4];
            float x0 = fmaf(q0.x, s0, m0);
            float x1 = fmaf(q0.y, s1, m1);
            float v0 = fmaf(q1.y, s5, m5);
            float v1 = fmaf(q2.x, s6, m6);
            float v2 = fmaf(q2.y, s7, m7);
            float v3 = fmaf(q3.x, s8, m8);
            const int jp = j >> 1, h = j & 1;
            f01[jp * 4 + h]     = v0;
            f01[jp * 4 + 2 + h] = v1;
            f23[jp * 4 + h]     = v2;
            f23[jp * 4 + 2 + h] = v3;
            fbb[j] = v0 * v0 + v1 * v1 + v2 * v2 + v3 * v3;
            sxy[j] = make_float2(x0, x1);
            slotj[j] = ~0ull;
        }
    }

    // ---- Owned states: thread t owns i in [8t, 8t+8) (ascending) ----
    ull a0d[ITEMS], a1d[ITEMS], a2d[ITEMS], a3d[ITEMS];
    float aa[ITEMS];
#pragma unroll
    for (int k = 0; k < ITEMS; k++) {
        const int i = tid * ITEMS + k;
        const float2* r2 = (const float2*)(ownp + (size_t)i * 10);
        const float2 q1 = r2[2];
        const float2 q2 = r2[3];
        const float2 q3 = r2[4];
        float a0 = fmaf(q1.y, s5, m5);
        float a1 = fmaf(q2.x, s6, m6);
        float a2 = fmaf(q2.y, s7, m7);
        float a3 = fmaf(q3.x, s8, m8);
        aa[k] = a0 * a0 + a1 * a1 + a2 * a2 + a3 * a3;
        a0d[k] = pack_dup(-2.0f * a0);
        a1d[k] = pack_dup(-2.0f * a1);
        a2d[k] = pack_dup(-2.0f * a2);
        a3d[k] = pack_dup(-2.0f * a3);
    }

    __syncthreads();

    // ---- Main loop: full d(i,j); per-state chunk min; per-goal lex-min ----
    float bestd[ITEMS];
    ull bcp = 0;                    // 8 x 6-bit packed chunk ids
#pragma unroll
    for (int k = 0; k < ITEMS; k++) bestd[k] = 3.4e38f;

    for (int ch = 0; ch < NCHUNK; ch++) {
        float cm[ITEMS];
#pragma unroll
        for (int k = 0; k < ITEMS; k++) cm[k] = 3.4e38f;

#pragma unroll
        for (int u = 0; u < CJP; u++) {
            const int jp = ch * CJP + u;
            const ulonglong2 p01 = sb01[jp];
            const ulonglong2 p23 = sb23[jp];
            const ull        acc = sbb[jp];

            float bv0 = 3.4e38f, bv1 = 3.4e38f;
            int   bk0 = 0,       bk1 = 0;
#pragma unroll
            for (int k = 0; k < ITEMS; k++) {
                ull t;
                FMA2(t, a0d[k], p01.x, acc);
                FMA2(t, a1d[k], p01.y, t);
                FMA2(t, a2d[k], p23.x, t);
                FMA2(t, a3d[k], p23.y, t);
                float lo, hi;
                unpack2(t, lo, hi);              // register-naming only
                const float dlo = lo + aa[k];    // full d(i, j0)
                const float dhi = hi + aa[k];    // full d(i, j1)
                // per-state (over goals): value-only chunk min
                cm[k] = fminf(cm[k], fminf(dlo, dhi));
                // per-goal (over states): ascending k, strict < keeps first i
                if (dlo < bv0) { bv0 = dlo; bk0 = k; }
                if (dhi < bv1) { bv1 = dhi; bk1 = k; }
            }

            // Cross-lane exact lex-min for the two goals of this jp.
            const int ic0 = tid * ITEMS + bk0;
            const int ic1 = tid * ITEMS + bk1;
            float w0 = bv0, w1 = bv1;
#pragma unroll
            for (int off = 16; off > 0; off >>= 1) {
                w0 = fminf(w0, __shfl_xor_sync(0xffffffffu, w0, off));
                w1 = fminf(w1, __shfl_xor_sync(0xffffffffu, w1, off));
            }
            const unsigned win0 = __ballot_sync(0xffffffffu, bv0 == w0);
            const unsigned win1 = __ballot_sync(0xffffffffu, bv1 == w1);
            const int i0 = __shfl_sync(0xffffffffu, ic0, __ffs(win0) - 1);
            const int i1 = __shfl_sync(0xffffffffu, ic1, __ffs(win1) - 1);
            if (lane == 0) {
                const ull k0 = ((ull)mono_f32(w0) << 32) | (unsigned)i0;
                const ull k1 = ((ull)mono_f32(w1) << 32) | (unsigned)i1;
                atomicMin(&slotj[jp * 2],     k0);   // lex (value, first-i) min
                atomicMin(&slotj[jp * 2 + 1], k1);
            }
        }
#pragma unroll
        for (int k = 0; k < ITEMS; k++) {
            if (cm[k] < bestd[k]) {                  // strict <: first chunk wins
                bestd[k] = cm[k];
                bcp = (bcp & ~(63ull << (k * 6))) | ((ull)(unsigned)ch << (k * 6));
            }
        }
    }

    // ---- Per-state tail: rescan winner chunk (identical op order), xd ----
    float partial = 0.0f;
#pragma unroll
    for (int k = 0; k < ITEMS; k++) {
        const int i = tid * ITEMS + k;
        const float2* r2 = (const float2*)(ownp + (size_t)i * 10);
        const float2 q0 = r2[0];
        const float ox = fmaf(q0.x, s0, m0);
        const float oy = fmaf(q0.y, s1, m1);

        const float bd = bestd[k];
        const int jp0 = (int)((bcp >> (k * 6)) & 63ull) * CJP;
        int jbest = jp0 * 2;
        bool found = false;
        for (int u = 0; u < CJP; u++) {
            const int jp = jp0 + u;
            const ulonglong2 p01 = sb01[jp];
            const ulonglong2 p23 = sb23[jp];
            const ull        acc = sbb[jp];
            ull t;
            FMA2(t, a0d[k], p01.x, acc);
            FMA2(t, a1d[k], p01.y, t);
            FMA2(t, a2d[k], p23.x, t);
            FMA2(t, a3d[k], p23.y, t);
            float lo, hi;
            unpack2(t, lo, hi);
            const float dlo = lo + aa[k];
            const float dhi = hi + aa[k];
            if (!found && dlo == bd) { jbest = jp * 2;     found = true; }
            if (!found && dhi == bd) { jbest = jp * 2 + 1; found = true; }
        }

        const float2 p = sxy[jbest];
        const float dx = ox - p.x;
        const float dy = oy - p.y;
        float xd = sqrtf(dx * dx + dy * dy);
        if (bd > 6.0f) xd = 1.0f;           // LATENT_DIST_THRESHOLD (full d)
        partial += xd;
    }

    __syncthreads();   // all per-goal atomics complete & visible

    // ---- Per-goal tail: read slots, compute xd ----
    for (int r = 0; r < N_PART / THREADS; r++) {
        const int j = tid * (N_PART / THREADS) + r;
        const ull key = slotj[j];
        const float v = unmono_f32((unsigned)(key >> 32));
        const int ist = (int)(key & 0xFFFFFFFFull);
        float xd;
        if (v > 6.0f) {
            xd = 1.0f;
        } else {
            const float2 g = sxy[j];
            const float2 sq = *(const float2*)(ownp + (size_t)ist * 10);
            const float sx = fmaf(sq.x, s0, m0);
            const float sy = fmaf(sq.y, s1, m1);
            const float dx = g.x - sx;
            const float dy = g.y - sy;
            xd = sqrtf(dx * dx + dy * dy);
        }
        partial += xd;
    }

    // ---- Block reduce (deterministic) ----
#pragma unroll
    for (int off = 16; off > 0; off >>= 1)
        partial += __shfl_down_sync(0xffffffffu, partial, off);
    if (lane == 0) warp_sums[tid >> 5] = partial;
    __syncthreads();
    if (tid == 0) {
        float s = 0.0f;
#pragma unroll
        for (int w = 0; w < THREADS / 32; w++) s += warp_sums[w];
        g_partials[bv] = s;
        __threadfence();
        s_rank = atomicAdd(&g_arrived, 1u);   // last CTA reduces
    }
    __syncthreads();

    if (s_rank == NCTA - 1) {
        __threadfence();                    // acquire partials
        // 128 threads: one batch element each (4 view-partials).
        {
            float s = 0.0f;
#pragma unroll
            for (int t = 0; t < 4; t++) s += g_partials[tid * 4 + t];
            out[tid] = -s * (1.0f / (1024.0f * 8.0f));
        }
        __syncthreads();
        if (tid == 0) g_arrived = 0;        // reset for next graph replay
    }
}

extern "C" void kernel_launch(void* const* d_in, const int* in_sizes, int n_in,
                              void* d_out, int out_size)
{
    const float* achieved  = (const float*)d_in[0];
    const float* desired   = (const float*)d_in[1];
    const float* norm_mean = (const float*)d_in[2];
    const float* norm_std  = (const float*)d_in[3];
    float* out = (float*)d_out;

    chamfer_pass_kernel<<<NCTA, THREADS>>>(achieved, desired, norm_mean, norm_std, out);
}